// round 3
// baseline (speedup 1.0000x reference)
#include <cuda_runtime.h>
#include <math.h>

// TTTLinearAdaptation: B=4, H=16, S=8192, D=64, CHUNK=16 -> 64 sequences x 512 chunks.
// One CTA per (b,h). W[64x64] state held in SMEM for the whole scan.

namespace {
constexpr int Dd      = 64;
constexpr int Cc      = 16;
constexpr int NCH     = 512;   // 8192 / 16
constexpr int THREADS = 256;
constexpr int NUM_BH  = 64;
}

__device__ __forceinline__ void cp_async16(void* sm, const void* gm) {
    unsigned a = (unsigned)__cvta_generic_to_shared(sm);
    asm volatile("cp.async.cg.shared.global [%0], [%1], 16;" :: "r"(a), "l"(gm));
}

__global__ void __launch_bounds__(THREADS, 1)
ttt_linear_kernel(const float* __restrict__ xq, const float* __restrict__ xk,
                  const float* __restrict__ xv, const float* __restrict__ W0,
                  const float* __restrict__ b0, const float* __restrict__ gamma_,
                  const float* __restrict__ beta_, const float* __restrict__ theta_,
                  const float* __restrict__ theta_bias, const float* __restrict__ alpha,
                  float* __restrict__ out)
{
    __shared__ float  W_s[Dd * Dd];            // 16 KB, persistent state
    __shared__ float4 buf[2][3 * Cc * Dd / 4]; // double-buffered q,k,v tiles (24 KB)
    __shared__ float  gx_s[Cc * Dd];           // grad_x (4 KB)
    __shared__ float  b_s[Dd], gm_s[Dd], bt_s[Dd], th_s[Dd];
    __shared__ float  eta_s[Cc], tok_s[Cc];

    const int tid = threadIdx.x;
    const int bh  = blockIdx.x;
    const int h   = bh & 15;
    const size_t base = (size_t)bh * (size_t)(NCH * Cc * Dd);

    // ---- init persistent state ----
    for (int i = tid; i < Dd * Dd; i += THREADS) W_s[i] = W0[h * Dd * Dd + i];
    if (tid < Dd) {
        b_s[tid]  = b0[h * Dd + tid];
        gm_s[tid] = gamma_[h * Dd + tid];
        bt_s[tid] = beta_[h * Dd + tid];
        th_s[tid] = theta_[h * Dd + tid];
    }
    if (tid < Cc) tok_s[tid] = fmaxf(1.0f / (float)(tid + 1) + alpha[tid], 0.0f);
    const float tb = __ldg(theta_bias + h);

    // ---- prefetch chunk 0 ----
    cp_async16(&buf[0][0 * 256 + tid], (const float4*)(xq + base) + tid);
    cp_async16(&buf[0][1 * 256 + tid], (const float4*)(xk + base) + tid);
    cp_async16(&buf[0][2 * 256 + tid], (const float4*)(xv + base) + tid);
    asm volatile("cp.async.commit_group;");
    __syncthreads();

    const int c  = tid >> 4;   // chunk row 0..15
    const int eg = tid & 15;   // column group: cols 4*eg .. 4*eg+3

    for (int i = 0; i < NCH; ++i) {
        // ---- prefetch next chunk (double buffer) ----
        {
            const int    ni = (i + 1 < NCH) ? (i + 1) : (NCH - 1);
            const int    nb = (i + 1) & 1;
            const size_t no = base + (size_t)ni * (Cc * Dd);
            cp_async16(&buf[nb][0 * 256 + tid], (const float4*)(xq + no) + tid);
            cp_async16(&buf[nb][1 * 256 + tid], (const float4*)(xk + no) + tid);
            cp_async16(&buf[nb][2 * 256 + tid], (const float4*)(xv + no) + tid);
            asm volatile("cp.async.commit_group;");
        }
        asm volatile("cp.async.wait_group 1;");
        __syncthreads();

        const float* q_s = (const float*)&buf[i & 1][0];
        const float* k_s = (const float*)&buf[i & 1][256];
        const float* v_s = (const float*)&buf[i & 1][512];

        // ============ Z = k @ W + b ============
        float a0 = 0.f, a1 = 0.f, a2 = 0.f, a3 = 0.f;
        const float* krow = k_s + c * Dd;
        #pragma unroll
        for (int d = 0; d < Dd; ++d) {
            const float  kv = krow[d];
            const float4 w  = *(const float4*)(W_s + d * Dd + eg * 4);
            a0 = fmaf(kv, w.x, a0);
            a1 = fmaf(kv, w.y, a1);
            a2 = fmaf(kv, w.z, a2);
            a3 = fmaf(kv, w.w, a3);
        }
        const float4 bv = *(const float4*)(b_s + eg * 4);
        const float z0 = a0 + bv.x, z1 = a1 + bv.y, z2 = a2 + bv.z, z3 = a3 + bv.w;

        // partial k . theta over this thread's 4 dims
        const float4 kl = *(const float4*)(krow + eg * 4);
        const float4 tl = *(const float4*)(th_s + eg * 4);
        float kth = kl.x * tl.x + kl.y * tl.y + kl.z * tl.z + kl.w * tl.w;

        // row reductions: sum(z), sum(z^2), k.theta  (16-lane butterfly)
        float s1 = z0 + z1 + z2 + z3;
        float s2 = z0 * z0 + z1 * z1 + z2 * z2 + z3 * z3;
        #pragma unroll
        for (int m = 8; m >= 1; m >>= 1) {
            s1  += __shfl_xor_sync(0xffffffffu, s1,  m);
            s2  += __shfl_xor_sync(0xffffffffu, s2,  m);
            kth += __shfl_xor_sync(0xffffffffu, kth, m);
        }
        const float mu   = s1 * (1.0f / 64.0f);
        const float var  = s2 * (1.0f / 64.0f) - mu * mu;
        const float rstd = rsqrtf(fmaxf(var, 0.0f) + 1e-6f);

        // eta = (1/D) * sigmoid(k.theta + tb) * tok[c]
        const float eta = tok_s[c] * (1.0f / 64.0f) / (1.0f + __expf(-(kth + tb)));
        if (eg == 0) eta_s[c] = eta;

        const float4 gm = *(const float4*)(gm_s + eg * 4);
        const float4 bt = *(const float4*)(bt_s + eg * 4);
        const float4 vv = *(const float4*)(v_s + c * Dd + eg * 4);

        const float xh0 = (z0 - mu) * rstd;
        const float xh1 = (z1 - mu) * rstd;
        const float xh2 = (z2 - mu) * rstd;
        const float xh3 = (z3 - mu) * rstd;
        const float y0 = fmaf(gm.x, xh0, bt.x);
        const float y1 = fmaf(gm.y, xh1, bt.y);
        const float y2 = fmaf(gm.z, xh2, bt.z);
        const float y3 = fmaf(gm.w, xh3, bt.w);
        // g = (y - (v - k)) * gamma
        const float g0 = (y0 - (vv.x - kl.x)) * gm.x;
        const float g1 = (y1 - (vv.y - kl.y)) * gm.y;
        const float g2 = (y2 - (vv.z - kl.z)) * gm.z;
        const float g3 = (y3 - (vv.w - kl.w)) * gm.w;

        float sg  = g0 + g1 + g2 + g3;
        float sgx = g0 * xh0 + g1 * xh1 + g2 * xh2 + g3 * xh3;
        #pragma unroll
        for (int m = 8; m >= 1; m >>= 1) {
            sg  += __shfl_xor_sync(0xffffffffu, sg,  m);
            sgx += __shfl_xor_sync(0xffffffffu, sgx, m);
        }
        const float cf = rstd * (1.0f / 64.0f);   // 1/(D*std)
        float4 gx;
        gx.x = (64.0f * g0 - sg - xh0 * sgx) * cf;
        gx.y = (64.0f * g1 - sg - xh1 * sgx) * cf;
        gx.z = (64.0f * g2 - sg - xh2 * sgx) * cf;
        gx.w = (64.0f * g3 - sg - xh3 * sgx) * cf;
        *(float4*)(gx_s + c * Dd + eg * 4) = gx;
        __syncthreads();

        // ============ db and dW;  W -= dW, b -= db ============
        if (tid < Dd) {
            float db = 0.0f;
            #pragma unroll
            for (int cc = 0; cc < Cc; ++cc) db = fmaf(eta_s[cc], gx_s[cc * Dd + tid], db);
            b_s[tid] -= db;
        }
        {
            float acc00=0.f,acc01=0.f,acc02=0.f,acc03=0.f;
            float acc10=0.f,acc11=0.f,acc12=0.f,acc13=0.f;
            float acc20=0.f,acc21=0.f,acc22=0.f,acc23=0.f;
            float acc30=0.f,acc31=0.f,acc32=0.f,acc33=0.f;
            const int d0 = (tid >> 4) * 4;
            const int e0 = (tid & 15) * 4;
            #pragma unroll
            for (int cc = 0; cc < Cc; ++cc) {
                const float  ev = eta_s[cc];
                float4 kk = *(const float4*)(k_s  + cc * Dd + d0);
                const float4 gg = *(const float4*)(gx_s + cc * Dd + e0);
                kk.x *= ev; kk.y *= ev; kk.z *= ev; kk.w *= ev;
                acc00 = fmaf(kk.x, gg.x, acc00); acc01 = fmaf(kk.x, gg.y, acc01);
                acc02 = fmaf(kk.x, gg.z, acc02); acc03 = fmaf(kk.x, gg.w, acc03);
                acc10 = fmaf(kk.y, gg.x, acc10); acc11 = fmaf(kk.y, gg.y, acc11);
                acc12 = fmaf(kk.y, gg.z, acc12); acc13 = fmaf(kk.y, gg.w, acc13);
                acc20 = fmaf(kk.z, gg.x, acc20); acc21 = fmaf(kk.z, gg.y, acc21);
                acc22 = fmaf(kk.z, gg.z, acc22); acc23 = fmaf(kk.z, gg.w, acc23);
                acc30 = fmaf(kk.w, gg.x, acc30); acc31 = fmaf(kk.w, gg.y, acc31);
                acc32 = fmaf(kk.w, gg.z, acc32); acc33 = fmaf(kk.w, gg.w, acc33);
            }
            float4* wp0 = (float4*)(W_s + (d0 + 0) * Dd + e0);
            float4* wp1 = (float4*)(W_s + (d0 + 1) * Dd + e0);
            float4* wp2 = (float4*)(W_s + (d0 + 2) * Dd + e0);
            float4* wp3 = (float4*)(W_s + (d0 + 3) * Dd + e0);
            float4 w0 = *wp0, w1 = *wp1, w2 = *wp2, w3 = *wp3;
            w0.x -= acc00; w0.y -= acc01; w0.z -= acc02; w0.w -= acc03;
            w1.x -= acc10; w1.y -= acc11; w1.z -= acc12; w1.w -= acc13;
            w2.x -= acc20; w2.y -= acc21; w2.z -= acc22; w2.w -= acc23;
            w3.x -= acc30; w3.y -= acc31; w3.z -= acc32; w3.w -= acc33;
            *wp0 = w0; *wp1 = w1; *wp2 = w2; *wp3 = w3;
        }
        __syncthreads();

        // ============ Zq = q @ Wn + bn, yq = LN(Zq), out = q + yq ============
        float p0 = 0.f, p1 = 0.f, p2 = 0.f, p3 = 0.f;
        const float* qrow = q_s + c * Dd;
        #pragma unroll
        for (int d = 0; d < Dd; ++d) {
            const float  qv = qrow[d];
            const float4 w  = *(const float4*)(W_s + d * Dd + eg * 4);
            p0 = fmaf(qv, w.x, p0);
            p1 = fmaf(qv, w.y, p1);
            p2 = fmaf(qv, w.z, p2);
            p3 = fmaf(qv, w.w, p3);
        }
        const float4 bn = *(const float4*)(b_s + eg * 4);
        const float u0 = p0 + bn.x, u1 = p1 + bn.y, u2 = p2 + bn.z, u3 = p3 + bn.w;

        float t1 = u0 + u1 + u2 + u3;
        float t2 = u0 * u0 + u1 * u1 + u2 * u2 + u3 * u3;
        #pragma unroll
        for (int m = 8; m >= 1; m >>= 1) {
            t1 += __shfl_xor_sync(0xffffffffu, t1, m);
            t2 += __shfl_xor_sync(0xffffffffu, t2, m);
        }
        const float mu2   = t1 * (1.0f / 64.0f);
        const float var2  = t2 * (1.0f / 64.0f) - mu2 * mu2;
        const float rstd2 = rsqrtf(fmaxf(var2, 0.0f) + 1e-6f);

        const float4 ql = *(const float4*)(qrow + eg * 4);
        float4 o;
        o.x = ql.x + fmaf(gm.x, (u0 - mu2) * rstd2, bt.x);
        o.y = ql.y + fmaf(gm.y, (u1 - mu2) * rstd2, bt.y);
        o.z = ql.z + fmaf(gm.z, (u2 - mu2) * rstd2, bt.z);
        o.w = ql.w + fmaf(gm.w, (u3 - mu2) * rstd2, bt.w);
        *(float4*)(out + base + (size_t)i * (Cc * Dd) + c * Dd + eg * 4) = o;

        __syncthreads();  // protect buf[i&1] before next-iter prefetch overwrites peer buffer
    }
    asm volatile("cp.async.wait_group 0;");
}

extern "C" void kernel_launch(void* const* d_in, const int* in_sizes, int n_in,
                              void* d_out, int out_size) {
    (void)in_sizes; (void)n_in; (void)out_size;
    const float* xq         = (const float*)d_in[0];
    const float* xk         = (const float*)d_in[1];
    const float* xv         = (const float*)d_in[2];
    const float* W0         = (const float*)d_in[3];
    const float* b0         = (const float*)d_in[4];
    const float* gamma_     = (const float*)d_in[5];
    const float* beta_      = (const float*)d_in[6];
    const float* theta_     = (const float*)d_in[7];
    const float* theta_bias = (const float*)d_in[8];
    const float* alpha      = (const float*)d_in[9];
    float* out = (float*)d_out;

    ttt_linear_kernel<<<NUM_BH, THREADS>>>(xq, xk, xv, W0, b0, gamma_, beta_,
                                           theta_, theta_bias, alpha, out);
}